// round 13
// baseline (speedup 1.0000x reference)
#include <cuda_runtime.h>
#include <cuda_fp16.h>

#define EPSV 1e-5f

// ---------------- scratch (device globals; no allocation allowed) ----------------
#define MAXN 100000
#define MAXG 500
#define MAXDEG 64   // Poisson(10): P(deg>64) ~ 1e-30

__device__ int      g_cnt_i[MAXN];              // in-degree / bin cursor
__device__ int      g_csc[MAXN * MAXDEG];       // fixed-stride CSC: src lists per dst
__device__ float    g_dis[MAXN];                // rsqrt(deg+1)
__device__ __half   g_hs1h[(MAXN + 1) * 64];    // (x@W1)*dis, fp16 ; row MAXN = zeros
__device__ __half   g_hs2h[(MAXN + 1) * 32];    // (y1@W2)*dis, fp16 ; row MAXN = zeros
__device__ unsigned g_W1p[32 * 64];             // W1 packed k-pair half2
__device__ unsigned g_W2p[32 * 32];             // W2 packed k-pair half2
__device__ float    g_sc1[64], g_sh1[64];       // BN1 folded scale/shift
__device__ float    g_sc2[32], g_sh2[32];       // BN2 folded scale/shift
__device__ float    g_sums[MAXG * 32];
__device__ float    g_cnt[MAXG];

// ---------------- binning: CSC build + zero pool accumulators (fused) ----------------
__global__ void bin_kernel(const int* __restrict__ ei, int nE) {
    int t = blockIdx.x * blockDim.x + threadIdx.x;
    if (t < MAXG * 32) g_sums[t] = 0.f;
    if (t < MAXG) g_cnt[t] = 0.f;
    if (t >= nE) return;
    int s = ei[t];
    int d = ei[nE + t];
    int p = atomicAdd(&g_cnt_i[d], 1);
    if (p < MAXDEG) g_csc[(size_t)d * MAXDEG + p] = s;
}

// ---------------- pad: CSC dummy-fill (8-node groups) + W packing + consts ---------
__global__ void pad_kernel(const float* __restrict__ W1, const float* __restrict__ W2,
                           const float* __restrict__ b1, const float* __restrict__ g1,
                           const float* __restrict__ be1, const float* __restrict__ m1,
                           const float* __restrict__ v1,
                           const float* __restrict__ b2, const float* __restrict__ g2,
                           const float* __restrict__ be2, const float* __restrict__ m2,
                           const float* __restrict__ v2, int n) {
    int t = blockIdx.x * blockDim.x + threadIdx.x;
    if (t < 64) g_hs1h[(size_t)MAXN * 64 + t] = __float2half(0.f);
    if (t < 32) g_hs2h[(size_t)MAXN * 32 + t] = __float2half(0.f);
    if (t < 2048) {  // W1[64][64] -> g_W1p[(k/2)*64 + c]
        int p = t >> 6, c = t & 63;
        __half2 h = __floats2half2_rn(W1[(2 * p) * 64 + c], W1[(2 * p + 1) * 64 + c]);
        g_W1p[t] = *reinterpret_cast<unsigned*>(&h);
    }
    if (t < 1024) {  // W2[64][32] -> g_W2p[(k/2)*32 + c]
        int p = t >> 5, c = t & 31;
        __half2 h = __floats2half2_rn(W2[(2 * p) * 32 + c], W2[(2 * p + 1) * 32 + c]);
        g_W2p[t] = *reinterpret_cast<unsigned*>(&h);
    }
    if (t < 64) {
        float s = g1[t] * rsqrtf(v1[t] + EPSV);
        g_sc1[t] = s;
        g_sh1[t] = (b1[t] - m1[t]) * s + be1[t];
    }
    if (t < 32) {
        float s = g2[t] * rsqrtf(v2[t] + EPSV);
        g_sc2[t] = s;
        g_sh2[t] = (b2[t] - m2[t]) * s + be2[t];
    }
    if (t >= n) return;

    g_dis[t] = rsqrtf((float)g_cnt_i[t] + 1.0f);

    // pad over 8-node groups (covers pull2's oct grouping; pull1's quad bound is smaller)
    int q0 = t & ~7;
    int maxd = 0;
#pragma unroll
    for (int k = 0; k < 8; k++) {
        int u = q0 + k;
        int du = (u < n) ? min(g_cnt_i[u], MAXDEG) : 0;
        maxd = max(maxd, du);
    }
    int dpad = min((maxd + 3) & ~3, MAXDEG);
    int d = min(g_cnt_i[t], MAXDEG);
    int* row = &g_csc[(size_t)t * MAXDEG];
    for (int p = d; p < dpad; p++) row[p] = MAXN;
}

// ---------------- layer-1 GEMM via tensor cores ----------------
__global__ void __launch_bounds__(256) gemm1_kernel(const float* __restrict__ X, int n) {
    int wp = threadIdx.x >> 5, lane = threadIdx.x & 31;
    int g = lane >> 2, tg = lane & 3;
    int r0 = blockIdx.x * 128 + wp * 16;
    if (r0 >= n) return;
    int rA = min(r0 + g, n - 1);
    int rB = min(r0 + g + 8, n - 1);
    const float* xA = &X[(size_t)rA * 64];
    const float* xB = &X[(size_t)rB * 64];

    float dfr[8][4];
#pragma unroll
    for (int ns = 0; ns < 8; ns++)
#pragma unroll
        for (int j = 0; j < 4; j++) dfr[ns][j] = 0.f;

#pragma unroll
    for (int ks = 0; ks < 4; ks++) {
        float2 fA0 = *reinterpret_cast<const float2*>(&xA[ks * 16 + 2 * tg]);
        float2 fB0 = *reinterpret_cast<const float2*>(&xB[ks * 16 + 2 * tg]);
        float2 fA1 = *reinterpret_cast<const float2*>(&xA[ks * 16 + 2 * tg + 8]);
        float2 fB1 = *reinterpret_cast<const float2*>(&xB[ks * 16 + 2 * tg + 8]);
        __half2 hA0 = __floats2half2_rn(fA0.x, fA0.y);
        __half2 hB0 = __floats2half2_rn(fB0.x, fB0.y);
        __half2 hA1 = __floats2half2_rn(fA1.x, fA1.y);
        __half2 hB1 = __floats2half2_rn(fB1.x, fB1.y);
        unsigned a0 = *reinterpret_cast<unsigned*>(&hA0);
        unsigned a1 = *reinterpret_cast<unsigned*>(&hB0);
        unsigned a2 = *reinterpret_cast<unsigned*>(&hA1);
        unsigned a3 = *reinterpret_cast<unsigned*>(&hB1);
#pragma unroll
        for (int ns = 0; ns < 8; ns++) {
            unsigned b0 = g_W1p[(ks * 8 + tg) * 64 + ns * 8 + g];
            unsigned b1 = g_W1p[(ks * 8 + tg + 4) * 64 + ns * 8 + g];
            asm volatile(
                "mma.sync.aligned.m16n8k16.row.col.f32.f16.f16.f32 "
                "{%0,%1,%2,%3}, {%4,%5,%6,%7}, {%8,%9}, {%0,%1,%2,%3};"
                : "+f"(dfr[ns][0]), "+f"(dfr[ns][1]), "+f"(dfr[ns][2]), "+f"(dfr[ns][3])
                : "r"(a0), "r"(a1), "r"(a2), "r"(a3), "r"(b0), "r"(b1));
        }
    }

    float dvA = g_dis[rA];
    float dvB = g_dis[rB];
    bool okA = (r0 + g) < n, okB = (r0 + g + 8) < n;
#pragma unroll
    for (int ns = 0; ns < 8; ns++) {
        int c = ns * 8 + 2 * tg;
        if (okA) {
            __half2 h = __floats2half2_rn(dfr[ns][0] * dvA, dfr[ns][1] * dvA);
            *reinterpret_cast<__half2*>(&g_hs1h[(size_t)rA * 64 + c]) = h;
        }
        if (okB) {
            __half2 h = __floats2half2_rn(dfr[ns][2] * dvB, dfr[ns][3] * dvB);
            *reinterpret_cast<__half2*>(&g_hs1h[(size_t)rB * 64 + c]) = h;
        }
    }
}

// accumulate one uint4 (8 halves) into 4 half2 accumulators
__device__ __forceinline__ void acc8(__half2* acc, const uint4& u) {
    acc[0] = __hadd2(acc[0], *reinterpret_cast<const __half2*>(&u.x));
    acc[1] = __hadd2(acc[1], *reinterpret_cast<const __half2*>(&u.y));
    acc[2] = __hadd2(acc[2], *reinterpret_cast<const __half2*>(&u.z));
    acc[3] = __hadd2(acc[3], *reinterpret_cast<const __half2*>(&u.w));
}

// ---------------- fused pull-1 + tensor-core GEMM-2 ----------------
// Phase 1: 4 nodes/warp, 8 lanes/node, LDG.128 gathers, DOUBLE-BUFFERED pipeline
//          (next quad's gathers in flight while accumulating current quad).
// Phase 2: 8 warps = 2 mtiles x 4 n-slices; 32x32x64 HMMA GEMM.
__global__ void __launch_bounds__(256) pull1_gemm2_kernel(int n) {
    __shared__ __half sy1h[32][72];   // 4.5 KB; 144B row stride

    int tid = threadIdx.x;
    int wp = tid >> 5;
    int lane = tid & 31;
    int q = lane >> 3;
    int li = lane & 7;

    int nodeIdx = blockIdx.x * 32 + wp * 4 + q;
    int v = min(nodeIdx, n - 1);
    int d = min(g_cnt_i[v], MAXDEG);
    int dp = max(d, __shfl_xor_sync(0xffffffffu, d, 8));
    int dmax = max(dp, __shfl_xor_sync(0xffffffffu, dp, 16));
    int d4 = (dmax + 3) & ~3;        // <= oct-padded bound written by pad_kernel
    const int* row = &g_csc[(size_t)v * MAXDEG];
    const __half* hp = &g_hs1h[li * 8];

    __half2 z = __floats2half2_rn(0.f, 0.f);
    __half2 a[4] = {z, z, z, z};
    __half2 c[4] = {z, z, z, z};

    if (d4 > 0) {
        int4 s = *reinterpret_cast<const int4*>(row);
        uint4 u0 = *reinterpret_cast<const uint4*>(&hp[(size_t)s.x * 64]);
        uint4 u1 = *reinterpret_cast<const uint4*>(&hp[(size_t)s.y * 64]);
        uint4 u2 = *reinterpret_cast<const uint4*>(&hp[(size_t)s.z * 64]);
        uint4 u3 = *reinterpret_cast<const uint4*>(&hp[(size_t)s.w * 64]);
        for (int i = 4; i < d4; i += 4) {
            int4 sn = *reinterpret_cast<const int4*>(row + i);
            uint4 v0 = *reinterpret_cast<const uint4*>(&hp[(size_t)sn.x * 64]);
            uint4 v1 = *reinterpret_cast<const uint4*>(&hp[(size_t)sn.y * 64]);
            uint4 v2 = *reinterpret_cast<const uint4*>(&hp[(size_t)sn.z * 64]);
            uint4 v3 = *reinterpret_cast<const uint4*>(&hp[(size_t)sn.w * 64]);
            acc8(a, u0); acc8(c, u1); acc8(a, u2); acc8(c, u3);
            u0 = v0; u1 = v1; u2 = v2; u3 = v3;
        }
        acc8(a, u0); acc8(c, u1); acc8(a, u2); acc8(c, u3);
    }

    // epilogue: y1 = relu(BN(dis * (agg + hs1[v])))
    float dvp = g_dis[v];
    uint4 uv = *reinterpret_cast<const uint4*>(&g_hs1h[(size_t)v * 64 + li * 8]);
    const __half2* hvp = reinterpret_cast<const __half2*>(&uv);
    float4 sc0 = *reinterpret_cast<const float4*>(&g_sc1[li * 8]);
    float4 sc1 = *reinterpret_cast<const float4*>(&g_sc1[li * 8 + 4]);
    float4 sh0 = *reinterpret_cast<const float4*>(&g_sh1[li * 8]);
    float4 sh1 = *reinterpret_cast<const float4*>(&g_sh1[li * 8 + 4]);
    float scv[8] = {sc0.x, sc0.y, sc0.z, sc0.w, sc1.x, sc1.y, sc1.z, sc1.w};
    float shv[8] = {sh0.x, sh0.y, sh0.z, sh0.w, sh1.x, sh1.y, sh1.z, sh1.w};
    __half2 pk[4];
#pragma unroll
    for (int k = 0; k < 4; k++) {
        float2 fa = __half22float2(a[k]);
        float2 fc = __half22float2(c[k]);
        float2 fv = __half22float2(hvp[k]);
        float y0 = fmaxf(dvp * (fa.x + fc.x + fv.x) * scv[2 * k] + shv[2 * k], 0.f);
        float y1 = fmaxf(dvp * (fa.y + fc.y + fv.y) * scv[2 * k + 1] + shv[2 * k + 1], 0.f);
        pk[k] = __floats2half2_rn(y0, y1);
    }
    int slot = wp * 4 + q;
    *reinterpret_cast<uint4*>(&sy1h[slot][li * 8]) = *reinterpret_cast<uint4*>(pk);
    __syncthreads();

    // ---- phase 2: 8 warps = 2 mtiles x 4 n-slices; HMMA m16n8k16 over K=64 ----
    int mtile = wp >> 2;
    int ns = wp & 3;
    int base = blockIdx.x * 32 + mtile * 16;
    int g = lane >> 2, tg = lane & 3;
    const __half(*sa)[72] = &sy1h[mtile * 16];

    float dfr[4] = {0.f, 0.f, 0.f, 0.f};
#pragma unroll
    for (int ks = 0; ks < 4; ks++) {
        unsigned afr0 = *reinterpret_cast<const unsigned*>(&sa[g][ks * 16 + 2 * tg]);
        unsigned afr1 = *reinterpret_cast<const unsigned*>(&sa[g + 8][ks * 16 + 2 * tg]);
        unsigned afr2 = *reinterpret_cast<const unsigned*>(&sa[g][ks * 16 + 2 * tg + 8]);
        unsigned afr3 = *reinterpret_cast<const unsigned*>(&sa[g + 8][ks * 16 + 2 * tg + 8]);
        unsigned b0 = g_W2p[(ks * 8 + tg) * 32 + ns * 8 + g];
        unsigned b1 = g_W2p[(ks * 8 + tg + 4) * 32 + ns * 8 + g];
        asm volatile(
            "mma.sync.aligned.m16n8k16.row.col.f32.f16.f16.f32 "
            "{%0,%1,%2,%3}, {%4,%5,%6,%7}, {%8,%9}, {%0,%1,%2,%3};"
            : "+f"(dfr[0]), "+f"(dfr[1]), "+f"(dfr[2]), "+f"(dfr[3])
            : "r"(afr0), "r"(afr1), "r"(afr2), "r"(afr3), "r"(b0), "r"(b1));
    }

    int nodeLo = base + g;
    int nodeHi = base + g + 8;
    int c0i = ns * 8 + 2 * tg;
    if (nodeLo < n) {
        float dvLo = g_dis[nodeLo];
        __half2 h = __floats2half2_rn(dfr[0] * dvLo, dfr[1] * dvLo);
        *reinterpret_cast<__half2*>(&g_hs2h[(size_t)nodeLo * 32 + c0i]) = h;
    }
    if (nodeHi < n) {
        float dvHi = g_dis[nodeHi];
        __half2 h = __floats2half2_rn(dfr[2] * dvHi, dfr[3] * dvHi);
        *reinterpret_cast<__half2*>(&g_hs2h[(size_t)nodeHi * 32 + c0i]) = h;
    }
}

// ---------------- fused pull-2 + mean-pool ----------------
// 8 nodes/warp, 4 lanes/node, lane owns 8 cols (LDG.128), double-buffered pipeline.
__global__ void __launch_bounds__(256) pull2_pool_kernel(const int* __restrict__ batch, int n) {
    int wid = (blockIdx.x * blockDim.x + threadIdx.x) >> 5;
    if (wid * 8 >= n) return;
    int lane = threadIdx.x & 31;
    int q = lane >> 2;               // node within warp (0..7)
    int li = lane & 3;               // owns cols li*8 .. li*8+7

    int vraw = wid * 8 + q;
    int v = min(vraw, n - 1);
    int d = min(g_cnt_i[v], MAXDEG);
    int d1 = max(d, __shfl_xor_sync(0xffffffffu, d, 4));
    int d2 = max(d1, __shfl_xor_sync(0xffffffffu, d1, 8));
    int dmax = max(d2, __shfl_xor_sync(0xffffffffu, d2, 16));
    int d4 = (dmax + 3) & ~3;        // == oct-padded bound (warp's 8 nodes = pad group)
    const int* row = &g_csc[(size_t)v * MAXDEG];
    const __half* hp = &g_hs2h[li * 8];

    __half2 z = __floats2half2_rn(0.f, 0.f);
    __half2 a[4] = {z, z, z, z};
    __half2 c[4] = {z, z, z, z};

    if (d4 > 0) {
        int4 s = *reinterpret_cast<const int4*>(row);
        uint4 u0 = *reinterpret_cast<const uint4*>(&hp[(size_t)s.x * 32]);
        uint4 u1 = *reinterpret_cast<const uint4*>(&hp[(size_t)s.y * 32]);
        uint4 u2 = *reinterpret_cast<const uint4*>(&hp[(size_t)s.z * 32]);
        uint4 u3 = *reinterpret_cast<const uint4*>(&hp[(size_t)s.w * 32]);
        for (int i = 4; i < d4; i += 4) {
            int4 sn = *reinterpret_cast<const int4*>(row + i);
            uint4 v0 = *reinterpret_cast<const uint4*>(&hp[(size_t)sn.x * 32]);
            uint4 v1 = *reinterpret_cast<const uint4*>(&hp[(size_t)sn.y * 32]);
            uint4 v2 = *reinterpret_cast<const uint4*>(&hp[(size_t)sn.z * 32]);
            uint4 v3 = *reinterpret_cast<const uint4*>(&hp[(size_t)sn.w * 32]);
            acc8(a, u0); acc8(c, u1); acc8(a, u2); acc8(c, u3);
            u0 = v0; u1 = v1; u2 = v2; u3 = v3;
        }
        acc8(a, u0); acc8(c, u1); acc8(a, u2); acc8(c, u3);
    }

    if (vraw >= n) return;

    float dv = g_dis[v];
    uint4 uv = *reinterpret_cast<const uint4*>(&g_hs2h[(size_t)v * 32 + li * 8]);
    const __half2* hvp = reinterpret_cast<const __half2*>(&uv);
    float4 sc0 = *reinterpret_cast<const float4*>(&g_sc2[li * 8]);
    float4 sc1 = *reinterpret_cast<const float4*>(&g_sc2[li * 8 + 4]);
    float4 sh0 = *reinterpret_cast<const float4*>(&g_sh2[li * 8]);
    float4 sh1 = *reinterpret_cast<const float4*>(&g_sh2[li * 8 + 4]);
    float scv[8] = {sc0.x, sc0.y, sc0.z, sc0.w, sc1.x, sc1.y, sc1.z, sc1.w};
    float shv[8] = {sh0.x, sh0.y, sh0.z, sh0.w, sh1.x, sh1.y, sh1.z, sh1.w};
    float o[8];
#pragma unroll
    for (int k = 0; k < 4; k++) {
        float2 fa = __half22float2(a[k]);
        float2 fc = __half22float2(c[k]);
        float2 fv = __half22float2(hvp[k]);
        o[2 * k]     = fmaxf(dv * (fa.x + fc.x + fv.x) * scv[2 * k] + shv[2 * k], 0.f);
        o[2 * k + 1] = fmaxf(dv * (fa.y + fc.y + fv.y) * scv[2 * k + 1] + shv[2 * k + 1], 0.f);
    }

    int g = batch[v];
    float* ap0 = &g_sums[g * 32 + li * 8];
    asm volatile("red.global.add.v4.f32 [%0], {%1,%2,%3,%4};"
                 :: "l"(ap0), "f"(o[0]), "f"(o[1]), "f"(o[2]), "f"(o[3])
                 : "memory");
    asm volatile("red.global.add.v4.f32 [%0], {%1,%2,%3,%4};"
                 :: "l"(ap0 + 4), "f"(o[4]), "f"(o[5]), "f"(o[6]), "f"(o[7])
                 : "memory");
    if (li == 0) atomicAdd(&g_cnt[g], 1.0f);
}

// ---------------- classifier ----------------
__global__ void classifier_kernel(const float* __restrict__ Wc1, const float* __restrict__ bc1,
                                  const float* __restrict__ Wc2, const float* __restrict__ bc2,
                                  float* __restrict__ out, int ngraphs) {
    __shared__ float sW1[32 * 16], sb1[16], sW2[16 * 2], sb2[2];
    int tid = threadIdx.x;
    if (tid < 512) sW1[tid] = Wc1[tid];
    if (tid < 16) sb1[tid] = bc1[tid];
    if (tid < 32) sW2[tid] = Wc2[tid];
    if (tid < 2) sb2[tid] = bc2[tid];
    __syncthreads();

    int g = tid;
    if (g >= ngraphs) return;
    float inv = 1.0f / fmaxf(g_cnt[g], 1.0f);
    float z[32];
#pragma unroll
    for (int f = 0; f < 32; f++) z[f] = g_sums[g * 32 + f] * inv;
    float o0 = sb2[0], o1 = sb2[1];
#pragma unroll
    for (int j = 0; j < 16; j++) {
        float h = sb1[j];
#pragma unroll
        for (int f = 0; f < 32; f++) h += z[f] * sW1[f * 16 + j];
        h = fmaxf(h, 0.f);
        o0 += h * sW2[j * 2 + 0];
        o1 += h * sW2[j * 2 + 1];
    }
    out[g * 2 + 0] = o0;
    out[g * 2 + 1] = o1;
}

// ---------------- launch ----------------
extern "C" void kernel_launch(void* const* d_in, const int* in_sizes, int n_in,
                              void* d_out, int out_size) {
    const float* x   = (const float*)d_in[0];
    const int*   ei  = (const int*)d_in[1];
    const int*   bat = (const int*)d_in[2];
    const float* W1  = (const float*)d_in[3];
    const float* b1  = (const float*)d_in[4];
    const float* g1  = (const float*)d_in[5];
    const float* be1 = (const float*)d_in[6];
    const float* m1  = (const float*)d_in[7];
    const float* v1  = (const float*)d_in[8];
    const float* W2  = (const float*)d_in[9];
    const float* b2  = (const float*)d_in[10];
    const float* g2  = (const float*)d_in[11];
    const float* be2 = (const float*)d_in[12];
    const float* m2  = (const float*)d_in[13];
    const float* v2  = (const float*)d_in[14];
    const float* Wc1 = (const float*)d_in[15];
    const float* bc1 = (const float*)d_in[16];
    const float* Wc2 = (const float*)d_in[17];
    const float* bc2 = (const float*)d_in[18];

    int n  = in_sizes[0] / 64;   // nodes
    int nE = in_sizes[1] / 2;    // edges
    int ngraphs = out_size / 2;

    void* p_cnti;
    cudaGetSymbolAddress(&p_cnti, g_cnt_i);
    cudaMemsetAsync(p_cnti, 0, (size_t)n * sizeof(int));

    bin_kernel<<<(nE + 255) / 256, 256>>>(ei, nE);
    pad_kernel<<<(n + 255) / 256, 256>>>(W1, W2, b1, g1, be1, m1, v1,
                                         b2, g2, be2, m2, v2, n);

    gemm1_kernel<<<(n + 127) / 128, 256>>>(x, n);
    pull1_gemm2_kernel<<<(n + 31) / 32, 256>>>(n);
    {
        int warps = (n + 7) / 8;
        pull2_pool_kernel<<<(warps * 32 + 255) / 256, 256>>>(bat, n);
    }
    classifier_kernel<<<1, 512>>>(Wc1, bc1, Wc2, bc2, (float*)d_out, ngraphs);
}

// round 14
// speedup vs baseline: 1.0164x; 1.0164x over previous
#include <cuda_runtime.h>
#include <cuda_fp16.h>

#define EPSV 1e-5f

// ---------------- scratch (device globals; no allocation allowed) ----------------
#define MAXN 100000
#define MAXG 500
#define MAXDEG 64   // Poisson(10): P(deg>64) ~ 1e-30

// g_cnt_i is SELF-CLEANING: zero-initialized at module load; pull2_pool re-zeroes
// it after its final read each call, so no memset node is needed in the graph.
__device__ int      g_cnt_i[MAXN];              // in-degree / bin cursor
__device__ int      g_csc[MAXN * MAXDEG];       // fixed-stride CSC: src lists per dst
__device__ float    g_dis[MAXN];                // rsqrt(deg+1)
__device__ __half   g_hs1h[(MAXN + 1) * 64];    // (x@W1)*dis, fp16 ; row MAXN = zeros
__device__ __half   g_hs2h[(MAXN + 1) * 32];    // (y1@W2)*dis, fp16 ; row MAXN = zeros
__device__ unsigned g_W1p[32 * 64];             // W1 packed k-pair half2
__device__ unsigned g_W2p[32 * 32];             // W2 packed k-pair half2
__device__ float    g_sc1[64], g_sh1[64];       // BN1 folded scale/shift
__device__ float    g_sc2[32], g_sh2[32];       // BN2 folded scale/shift
__device__ float    g_sums[MAXG * 32];
__device__ float    g_cnt[MAXG];

// ---------------- binning: CSC build + zero pool accumulators (fused) ----------------
__global__ void bin_kernel(const int* __restrict__ ei, int nE) {
    int t = blockIdx.x * blockDim.x + threadIdx.x;
    if (t < MAXG * 32) g_sums[t] = 0.f;
    if (t < MAXG) g_cnt[t] = 0.f;
    if (t >= nE) return;
    int s = ei[t];
    int d = ei[nE + t];
    int p = atomicAdd(&g_cnt_i[d], 1);
    if (p < MAXDEG) g_csc[(size_t)d * MAXDEG + p] = s;
}

// ---------------- pad: CSC dummy-fill (8-node groups) + W packing + consts ---------
__global__ void pad_kernel(const float* __restrict__ W1, const float* __restrict__ W2,
                           const float* __restrict__ b1, const float* __restrict__ g1,
                           const float* __restrict__ be1, const float* __restrict__ m1,
                           const float* __restrict__ v1,
                           const float* __restrict__ b2, const float* __restrict__ g2,
                           const float* __restrict__ be2, const float* __restrict__ m2,
                           const float* __restrict__ v2, int n) {
    int t = blockIdx.x * blockDim.x + threadIdx.x;
    if (t < 64) g_hs1h[(size_t)MAXN * 64 + t] = __float2half(0.f);
    if (t < 32) g_hs2h[(size_t)MAXN * 32 + t] = __float2half(0.f);
    if (t < 2048) {  // W1[64][64] -> g_W1p[(k/2)*64 + c]
        int p = t >> 6, c = t & 63;
        __half2 h = __floats2half2_rn(W1[(2 * p) * 64 + c], W1[(2 * p + 1) * 64 + c]);
        g_W1p[t] = *reinterpret_cast<unsigned*>(&h);
    }
    if (t < 1024) {  // W2[64][32] -> g_W2p[(k/2)*32 + c]
        int p = t >> 5, c = t & 31;
        __half2 h = __floats2half2_rn(W2[(2 * p) * 32 + c], W2[(2 * p + 1) * 32 + c]);
        g_W2p[t] = *reinterpret_cast<unsigned*>(&h);
    }
    if (t < 64) {
        float s = g1[t] * rsqrtf(v1[t] + EPSV);
        g_sc1[t] = s;
        g_sh1[t] = (b1[t] - m1[t]) * s + be1[t];
    }
    if (t < 32) {
        float s = g2[t] * rsqrtf(v2[t] + EPSV);
        g_sc2[t] = s;
        g_sh2[t] = (b2[t] - m2[t]) * s + be2[t];
    }
    if (t >= n) return;

    g_dis[t] = rsqrtf((float)g_cnt_i[t] + 1.0f);

    // pad over 8-node groups (covers pull2's oct grouping; pull1's quad bound smaller)
    int q0 = t & ~7;
    int maxd = 0;
#pragma unroll
    for (int k = 0; k < 8; k++) {
        int u = q0 + k;
        int du = (u < n) ? min(g_cnt_i[u], MAXDEG) : 0;
        maxd = max(maxd, du);
    }
    int dpad = min((maxd + 3) & ~3, MAXDEG);
    int d = min(g_cnt_i[t], MAXDEG);
    int* row = &g_csc[(size_t)t * MAXDEG];
    for (int p = d; p < dpad; p++) row[p] = MAXN;
}

// ---------------- layer-1 GEMM via tensor cores ----------------
__global__ void __launch_bounds__(256) gemm1_kernel(const float* __restrict__ X, int n) {
    int wp = threadIdx.x >> 5, lane = threadIdx.x & 31;
    int g = lane >> 2, tg = lane & 3;
    int r0 = blockIdx.x * 128 + wp * 16;
    if (r0 >= n) return;
    int rA = min(r0 + g, n - 1);
    int rB = min(r0 + g + 8, n - 1);
    const float* xA = &X[(size_t)rA * 64];
    const float* xB = &X[(size_t)rB * 64];

    float dfr[8][4];
#pragma unroll
    for (int ns = 0; ns < 8; ns++)
#pragma unroll
        for (int j = 0; j < 4; j++) dfr[ns][j] = 0.f;

#pragma unroll
    for (int ks = 0; ks < 4; ks++) {
        float2 fA0 = *reinterpret_cast<const float2*>(&xA[ks * 16 + 2 * tg]);
        float2 fB0 = *reinterpret_cast<const float2*>(&xB[ks * 16 + 2 * tg]);
        float2 fA1 = *reinterpret_cast<const float2*>(&xA[ks * 16 + 2 * tg + 8]);
        float2 fB1 = *reinterpret_cast<const float2*>(&xB[ks * 16 + 2 * tg + 8]);
        __half2 hA0 = __floats2half2_rn(fA0.x, fA0.y);
        __half2 hB0 = __floats2half2_rn(fB0.x, fB0.y);
        __half2 hA1 = __floats2half2_rn(fA1.x, fA1.y);
        __half2 hB1 = __floats2half2_rn(fB1.x, fB1.y);
        unsigned a0 = *reinterpret_cast<unsigned*>(&hA0);
        unsigned a1 = *reinterpret_cast<unsigned*>(&hB0);
        unsigned a2 = *reinterpret_cast<unsigned*>(&hA1);
        unsigned a3 = *reinterpret_cast<unsigned*>(&hB1);
#pragma unroll
        for (int ns = 0; ns < 8; ns++) {
            unsigned b0 = g_W1p[(ks * 8 + tg) * 64 + ns * 8 + g];
            unsigned b1 = g_W1p[(ks * 8 + tg + 4) * 64 + ns * 8 + g];
            asm volatile(
                "mma.sync.aligned.m16n8k16.row.col.f32.f16.f16.f32 "
                "{%0,%1,%2,%3}, {%4,%5,%6,%7}, {%8,%9}, {%0,%1,%2,%3};"
                : "+f"(dfr[ns][0]), "+f"(dfr[ns][1]), "+f"(dfr[ns][2]), "+f"(dfr[ns][3])
                : "r"(a0), "r"(a1), "r"(a2), "r"(a3), "r"(b0), "r"(b1));
        }
    }

    float dvA = g_dis[rA];
    float dvB = g_dis[rB];
    bool okA = (r0 + g) < n, okB = (r0 + g + 8) < n;
#pragma unroll
    for (int ns = 0; ns < 8; ns++) {
        int c = ns * 8 + 2 * tg;
        if (okA) {
            __half2 h = __floats2half2_rn(dfr[ns][0] * dvA, dfr[ns][1] * dvA);
            *reinterpret_cast<__half2*>(&g_hs1h[(size_t)rA * 64 + c]) = h;
        }
        if (okB) {
            __half2 h = __floats2half2_rn(dfr[ns][2] * dvB, dfr[ns][3] * dvB);
            *reinterpret_cast<__half2*>(&g_hs1h[(size_t)rB * 64 + c]) = h;
        }
    }
}

// accumulate one uint4 (8 halves) into 4 half2 accumulators
__device__ __forceinline__ void acc8(__half2* acc, const uint4& u) {
    acc[0] = __hadd2(acc[0], *reinterpret_cast<const __half2*>(&u.x));
    acc[1] = __hadd2(acc[1], *reinterpret_cast<const __half2*>(&u.y));
    acc[2] = __hadd2(acc[2], *reinterpret_cast<const __half2*>(&u.z));
    acc[3] = __hadd2(acc[3], *reinterpret_cast<const __half2*>(&u.w));
}

// ---------------- fused pull-1 + tensor-core GEMM-2 ----------------
// Phase 1: 4 nodes/warp, 8 lanes/node, LDG.128 gathers, simple int4 index prefetch
//          (R12 form — short loop, low regs; occupancy > pipelining here).
// Phase 2: 8 warps = 2 mtiles x 4 n-slices; 32x32x64 HMMA GEMM.
__global__ void __launch_bounds__(256, 6) pull1_gemm2_kernel(int n) {
    __shared__ __half sy1h[32][72];   // 4.5 KB; 144B row stride

    int tid = threadIdx.x;
    int wp = tid >> 5;
    int lane = tid & 31;
    int q = lane >> 3;
    int li = lane & 7;

    int nodeIdx = blockIdx.x * 32 + wp * 4 + q;
    int v = min(nodeIdx, n - 1);
    int d = min(g_cnt_i[v], MAXDEG);
    int dp = max(d, __shfl_xor_sync(0xffffffffu, d, 8));
    int dmax = max(dp, __shfl_xor_sync(0xffffffffu, dp, 16));
    int d4 = (dmax + 3) & ~3;        // <= oct-padded bound written by pad_kernel
    const int* row = &g_csc[(size_t)v * MAXDEG];
    const __half* hp = &g_hs1h[li * 8];

    __half2 z = __floats2half2_rn(0.f, 0.f);
    __half2 a[4] = {z, z, z, z};
    __half2 c[4] = {z, z, z, z};

    int4 s = *reinterpret_cast<const int4*>(row);   // prefetch (in-bounds; unused if d4==0)
    for (int i = 0; i < d4; i += 4) {
        int4 sn = (i + 4 < d4) ? *reinterpret_cast<const int4*>(row + i + 4) : s;
        uint4 u0 = *reinterpret_cast<const uint4*>(&hp[(size_t)s.x * 64]);
        uint4 u1 = *reinterpret_cast<const uint4*>(&hp[(size_t)s.y * 64]);
        uint4 u2 = *reinterpret_cast<const uint4*>(&hp[(size_t)s.z * 64]);
        uint4 u3 = *reinterpret_cast<const uint4*>(&hp[(size_t)s.w * 64]);
        acc8(a, u0); acc8(c, u1); acc8(a, u2); acc8(c, u3);
        s = sn;
    }

    // epilogue: y1 = relu(BN(dis * (agg + hs1[v])))
    float dvp = g_dis[v];
    uint4 uv = *reinterpret_cast<const uint4*>(&g_hs1h[(size_t)v * 64 + li * 8]);
    const __half2* hvp = reinterpret_cast<const __half2*>(&uv);
    float4 sc0 = *reinterpret_cast<const float4*>(&g_sc1[li * 8]);
    float4 sc1 = *reinterpret_cast<const float4*>(&g_sc1[li * 8 + 4]);
    float4 sh0 = *reinterpret_cast<const float4*>(&g_sh1[li * 8]);
    float4 sh1 = *reinterpret_cast<const float4*>(&g_sh1[li * 8 + 4]);
    float scv[8] = {sc0.x, sc0.y, sc0.z, sc0.w, sc1.x, sc1.y, sc1.z, sc1.w};
    float shv[8] = {sh0.x, sh0.y, sh0.z, sh0.w, sh1.x, sh1.y, sh1.z, sh1.w};
    __half2 pk[4];
#pragma unroll
    for (int k = 0; k < 4; k++) {
        float2 fa = __half22float2(a[k]);
        float2 fc = __half22float2(c[k]);
        float2 fv = __half22float2(hvp[k]);
        float y0 = fmaxf(dvp * (fa.x + fc.x + fv.x) * scv[2 * k] + shv[2 * k], 0.f);
        float y1 = fmaxf(dvp * (fa.y + fc.y + fv.y) * scv[2 * k + 1] + shv[2 * k + 1], 0.f);
        pk[k] = __floats2half2_rn(y0, y1);
    }
    int slot = wp * 4 + q;
    *reinterpret_cast<uint4*>(&sy1h[slot][li * 8]) = *reinterpret_cast<uint4*>(pk);
    __syncthreads();

    // ---- phase 2: 8 warps = 2 mtiles x 4 n-slices; HMMA m16n8k16 over K=64 ----
    int mtile = wp >> 2;
    int ns = wp & 3;
    int base = blockIdx.x * 32 + mtile * 16;
    int g = lane >> 2, tg = lane & 3;
    const __half(*sa)[72] = &sy1h[mtile * 16];

    float dfr[4] = {0.f, 0.f, 0.f, 0.f};
#pragma unroll
    for (int ks = 0; ks < 4; ks++) {
        unsigned afr0 = *reinterpret_cast<const unsigned*>(&sa[g][ks * 16 + 2 * tg]);
        unsigned afr1 = *reinterpret_cast<const unsigned*>(&sa[g + 8][ks * 16 + 2 * tg]);
        unsigned afr2 = *reinterpret_cast<const unsigned*>(&sa[g][ks * 16 + 2 * tg + 8]);
        unsigned afr3 = *reinterpret_cast<const unsigned*>(&sa[g + 8][ks * 16 + 2 * tg + 8]);
        unsigned b0 = g_W2p[(ks * 8 + tg) * 32 + ns * 8 + g];
        unsigned b1 = g_W2p[(ks * 8 + tg + 4) * 32 + ns * 8 + g];
        asm volatile(
            "mma.sync.aligned.m16n8k16.row.col.f32.f16.f16.f32 "
            "{%0,%1,%2,%3}, {%4,%5,%6,%7}, {%8,%9}, {%0,%1,%2,%3};"
            : "+f"(dfr[0]), "+f"(dfr[1]), "+f"(dfr[2]), "+f"(dfr[3])
            : "r"(afr0), "r"(afr1), "r"(afr2), "r"(afr3), "r"(b0), "r"(b1));
    }

    int nodeLo = base + g;
    int nodeHi = base + g + 8;
    int c0i = ns * 8 + 2 * tg;
    if (nodeLo < n) {
        float dvLo = g_dis[nodeLo];
        __half2 h = __floats2half2_rn(dfr[0] * dvLo, dfr[1] * dvLo);
        *reinterpret_cast<__half2*>(&g_hs2h[(size_t)nodeLo * 32 + c0i]) = h;
    }
    if (nodeHi < n) {
        float dvHi = g_dis[nodeHi];
        __half2 h = __floats2half2_rn(dfr[2] * dvHi, dfr[3] * dvHi);
        *reinterpret_cast<__half2*>(&g_hs2h[(size_t)nodeHi * 32 + c0i]) = h;
    }
}

// ---------------- fused pull-2 + mean-pool ----------------
// 8 nodes/warp, 4 lanes/node, LDG.128, simple prefetch loop. Last reader of
// g_cnt_i: lane 0 of each node zeroes it post-read (removes the memset node).
__global__ void __launch_bounds__(256, 6) pull2_pool_kernel(const int* __restrict__ batch, int n) {
    int wid = (blockIdx.x * blockDim.x + threadIdx.x) >> 5;
    if (wid * 8 >= n) return;
    int lane = threadIdx.x & 31;
    int q = lane >> 2;               // node within warp (0..7)
    int li = lane & 3;               // owns cols li*8 .. li*8+7

    int vraw = wid * 8 + q;
    int v = min(vraw, n - 1);
    int d = min(g_cnt_i[v], MAXDEG);
    int d1 = max(d, __shfl_xor_sync(0xffffffffu, d, 4));
    int d2 = max(d1, __shfl_xor_sync(0xffffffffu, d1, 8));
    int dmax = max(d2, __shfl_xor_sync(0xffffffffu, d2, 16));
    int d4 = (dmax + 3) & ~3;        // == oct-padded bound (warp's 8 nodes = pad group)
    // self-clean for next graph replay (all lanes have read; shfls are sync points)
    if (li == 0 && vraw < n) g_cnt_i[v] = 0;
    const int* row = &g_csc[(size_t)v * MAXDEG];
    const __half* hp = &g_hs2h[li * 8];

    __half2 z = __floats2half2_rn(0.f, 0.f);
    __half2 a[4] = {z, z, z, z};
    __half2 c[4] = {z, z, z, z};

    int4 s = *reinterpret_cast<const int4*>(row);
    for (int i = 0; i < d4; i += 4) {
        int4 sn = (i + 4 < d4) ? *reinterpret_cast<const int4*>(row + i + 4) : s;
        uint4 u0 = *reinterpret_cast<const uint4*>(&hp[(size_t)s.x * 32]);
        uint4 u1 = *reinterpret_cast<const uint4*>(&hp[(size_t)s.y * 32]);
        uint4 u2 = *reinterpret_cast<const uint4*>(&hp[(size_t)s.z * 32]);
        uint4 u3 = *reinterpret_cast<const uint4*>(&hp[(size_t)s.w * 32]);
        acc8(a, u0); acc8(c, u1); acc8(a, u2); acc8(c, u3);
        s = sn;
    }

    if (vraw >= n) return;

    float dv = g_dis[v];
    uint4 uv = *reinterpret_cast<const uint4*>(&g_hs2h[(size_t)v * 32 + li * 8]);
    const __half2* hvp = reinterpret_cast<const __half2*>(&uv);
    float4 sc0 = *reinterpret_cast<const float4*>(&g_sc2[li * 8]);
    float4 sc1 = *reinterpret_cast<const float4*>(&g_sc2[li * 8 + 4]);
    float4 sh0 = *reinterpret_cast<const float4*>(&g_sh2[li * 8]);
    float4 sh1 = *reinterpret_cast<const float4*>(&g_sh2[li * 8 + 4]);
    float scv[8] = {sc0.x, sc0.y, sc0.z, sc0.w, sc1.x, sc1.y, sc1.z, sc1.w};
    float shv[8] = {sh0.x, sh0.y, sh0.z, sh0.w, sh1.x, sh1.y, sh1.z, sh1.w};
    float o[8];
#pragma unroll
    for (int k = 0; k < 4; k++) {
        float2 fa = __half22float2(a[k]);
        float2 fc = __half22float2(c[k]);
        float2 fv = __half22float2(hvp[k]);
        o[2 * k]     = fmaxf(dv * (fa.x + fc.x + fv.x) * scv[2 * k] + shv[2 * k], 0.f);
        o[2 * k + 1] = fmaxf(dv * (fa.y + fc.y + fv.y) * scv[2 * k + 1] + shv[2 * k + 1], 0.f);
    }

    int g = batch[v];
    float* ap0 = &g_sums[g * 32 + li * 8];
    asm volatile("red.global.add.v4.f32 [%0], {%1,%2,%3,%4};"
                 :: "l"(ap0), "f"(o[0]), "f"(o[1]), "f"(o[2]), "f"(o[3])
                 : "memory");
    asm volatile("red.global.add.v4.f32 [%0], {%1,%2,%3,%4};"
                 :: "l"(ap0 + 4), "f"(o[4]), "f"(o[5]), "f"(o[6]), "f"(o[7])
                 : "memory");
    if (li == 0) atomicAdd(&g_cnt[g], 1.0f);
}

// ---------------- classifier ----------------
__global__ void classifier_kernel(const float* __restrict__ Wc1, const float* __restrict__ bc1,
                                  const float* __restrict__ Wc2, const float* __restrict__ bc2,
                                  float* __restrict__ out, int ngraphs) {
    __shared__ float sW1[32 * 16], sb1[16], sW2[16 * 2], sb2[2];
    int tid = threadIdx.x;
    if (tid < 512) sW1[tid] = Wc1[tid];
    if (tid < 16) sb1[tid] = bc1[tid];
    if (tid < 32) sW2[tid] = Wc2[tid];
    if (tid < 2) sb2[tid] = bc2[tid];
    __syncthreads();

    int g = tid;
    if (g >= ngraphs) return;
    float inv = 1.0f / fmaxf(g_cnt[g], 1.0f);
    float z[32];
#pragma unroll
    for (int f = 0; f < 32; f++) z[f] = g_sums[g * 32 + f] * inv;
    float o0 = sb2[0], o1 = sb2[1];
#pragma unroll
    for (int j = 0; j < 16; j++) {
        float h = sb1[j];
#pragma unroll
        for (int f = 0; f < 32; f++) h += z[f] * sW1[f * 16 + j];
        h = fmaxf(h, 0.f);
        o0 += h * sW2[j * 2 + 0];
        o1 += h * sW2[j * 2 + 1];
    }
    out[g * 2 + 0] = o0;
    out[g * 2 + 1] = o1;
}

// ---------------- launch ----------------
extern "C" void kernel_launch(void* const* d_in, const int* in_sizes, int n_in,
                              void* d_out, int out_size) {
    const float* x   = (const float*)d_in[0];
    const int*   ei  = (const int*)d_in[1];
    const int*   bat = (const int*)d_in[2];
    const float* W1  = (const float*)d_in[3];
    const float* b1  = (const float*)d_in[4];
    const float* g1  = (const float*)d_in[5];
    const float* be1 = (const float*)d_in[6];
    const float* m1  = (const float*)d_in[7];
    const float* v1  = (const float*)d_in[8];
    const float* W2  = (const float*)d_in[9];
    const float* b2  = (const float*)d_in[10];
    const float* g2  = (const float*)d_in[11];
    const float* be2 = (const float*)d_in[12];
    const float* m2  = (const float*)d_in[13];
    const float* v2  = (const float*)d_in[14];
    const float* Wc1 = (const float*)d_in[15];
    const float* bc1 = (const float*)d_in[16];
    const float* Wc2 = (const float*)d_in[17];
    const float* bc2 = (const float*)d_in[18];

    int n  = in_sizes[0] / 64;   // nodes
    int nE = in_sizes[1] / 2;    // edges
    int ngraphs = out_size / 2;

    // NOTE: no memset — g_cnt_i is zero at module load and re-zeroed by
    // pull2_pool_kernel at the end of every call (self-cleaning).
    bin_kernel<<<(nE + 255) / 256, 256>>>(ei, nE);
    pad_kernel<<<(n + 255) / 256, 256>>>(W1, W2, b1, g1, be1, m1, v1,
                                         b2, g2, be2, m2, v2, n);

    gemm1_kernel<<<(n + 127) / 128, 256>>>(x, n);
    pull1_gemm2_kernel<<<(n + 31) / 32, 256>>>(n);
    {
        int warps = (n + 7) / 8;
        pull2_pool_kernel<<<(warps * 32 + 255) / 256, 256>>>(bat, n);
    }
    classifier_kernel<<<1, 512>>>(Wc1, bc1, Wc2, bc2, (float*)d_out, ngraphs);
}